// round 17
// baseline (speedup 1.0000x reference)
#include <cuda_runtime.h>
#include <cuda_bf16.h>
#include <math.h>
#include <stdint.h>

#define Bb   4
#define Ls   4096
#define Dd   1024
#define Hh   64
#define ROWS (Bb*Ls)      // 16384
#define KCH  512
#define NCH  (Ls/KCH)     // 8

typedef unsigned long long u64;

// log2(e)/8 folded into Q so scores live in the log2 domain
#define QSCALE 0.18033688011112042f

__device__ float g_v  [ROWS*Hh];
__device__ float g_m  [NCH*ROWS];
__device__ float g_l  [NCH*ROWS];
__device__ float g_acc[(size_t)NCH*ROWS*Hh];
__device__ __nv_bfloat16 g_wh[192*Dd];
__device__ __nv_bfloat16 g_wl[192*Dd];
__device__ __nv_bfloat16 g_qh[ROWS*Hh], g_ql[ROWS*Hh];   // (Q*QSCALE) split, [row][dim]
__device__ __nv_bfloat16 g_kh[ROWS*Hh], g_kl[ROWS*Hh];   // K split,          [row][dim]
__device__ __nv_bfloat16 g_vh[ROWS*Hh], g_vl[ROWS*Hh];   // V^T split,        [b][dim][seq]

// ---- helpers ----------------------------------------------------------------
__device__ __forceinline__ uint32_t smem_u32(const void* p) {
    uint32_t a;
    asm("{ .reg .u64 t; cvta.to.shared.u64 t, %1; cvt.u32.u64 %0, t; }" : "=r"(a) : "l"(p));
    return a;
}
__device__ __forceinline__ void ldmx4(uint32_t r[4], uint32_t addr) {
    asm volatile("ldmatrix.sync.aligned.m8n8.x4.shared.b16 {%0,%1,%2,%3}, [%4];"
                 : "=r"(r[0]), "=r"(r[1]), "=r"(r[2]), "=r"(r[3]) : "r"(addr));
}
__device__ __forceinline__ void mma16816(float d[4], const uint32_t a[4],
                                         uint32_t b0, uint32_t b1) {
    asm volatile(
        "mma.sync.aligned.m16n8k16.row.col.f32.bf16.bf16.f32 "
        "{%0,%1,%2,%3}, {%4,%5,%6,%7}, {%8,%9}, {%0,%1,%2,%3};"
        : "+f"(d[0]), "+f"(d[1]), "+f"(d[2]), "+f"(d[3])
        : "r"(a[0]), "r"(a[1]), "r"(a[2]), "r"(a[3]), "r"(b0), "r"(b1));
}
__device__ __forceinline__ uint32_t swz_rj(int row, int j) {
    return (uint32_t)(row * 128 + ((j ^ (row & 7)) << 4));
}
__device__ __forceinline__ uint32_t swz_rb(int row, int bytecol) {
    return (uint32_t)(row * 128 + (bytecol ^ ((row & 7) << 4)));
}
__device__ __forceinline__ uint32_t bfpack(float x, float y) {
    __nv_bfloat162 t = __floats2bfloat162_rn(x, y);
    return *(uint32_t*)&t;
}
__device__ __forceinline__ float ex2(float x) {
    float r; asm("ex2.approx.ftz.f32 %0, %1;" : "=f"(r) : "f"(x)); return r;
}
#define CPA16(dst, src) asm volatile("cp.async.cg.shared.global [%0], [%1], 16;" :: "r"(dst), "l"(src) : "memory")
#define CPA_COMMIT()    asm volatile("cp.async.commit_group;" ::: "memory")
#define CPA_WAIT(n)     asm volatile("cp.async.wait_group %0;" :: "n"(n) : "memory")

// SMEM layout for proj (dynamic, bytes)
#define SM_AH 0
#define SM_AL 16384
#define SM_BH 32768
#define SM_BL 57344
#define SM_TOTAL 81920
// attnB: 2 x 32KB double buffer (Kh|Kl|Vh|Vl each 8KB); Q staged in buf region
#define ATT_SMEM 65536

// ---------------------------------------------------------------------------
__global__ __launch_bounds__(256) void prep_w_kernel(
    const float* __restrict__ Wq, const float* __restrict__ Wk,
    const float* __restrict__ Wv)
{
    int idx = blockIdx.x * 256 + threadIdx.x;
    int n = idx >> 10;
    int k = idx & 1023;
    const float* W = (n < 64) ? Wq : (n < 128) ? Wk : Wv;
    float x = W[(size_t)k * Hh + (n & 63)];
    __nv_bfloat16 h = __float2bfloat16(x);
    __nv_bfloat16 l = __float2bfloat16(x - __bfloat162float(h));
    g_wh[idx] = h;
    g_wl[idx] = l;
}

// ---------------------------------------------------------------------------
// Projection via mma.sync (unchanged — proven). Epilogue emits q/k split + v fp32.
// ---------------------------------------------------------------------------
__global__ __launch_bounds__(256, 1) void proj_mma_kernel(const float* __restrict__ X)
{
    extern __shared__ __align__(1024) char smem[];
    const uint32_t sAh = smem_u32(smem) + SM_AH;
    const uint32_t sAl = smem_u32(smem) + SM_AL;
    const uint32_t sBh = smem_u32(smem) + SM_BH;
    const uint32_t sBl = smem_u32(smem) + SM_BL;

    const int tid  = threadIdx.x;
    const int wid  = tid >> 5;
    const int lane = tid & 31;
    const int r0   = blockIdx.x * 128;
    const int m0   = (wid >> 2) * 64;
    const int n0   = (wid & 3) * 48;
    const int arow = lane & 15;
    const int ahalf = lane >> 4;

    float d[4][6][4];
#pragma unroll
    for (int mt = 0; mt < 4; mt++)
#pragma unroll
        for (int nt = 0; nt < 6; nt++)
#pragma unroll
            for (int e = 0; e < 4; e++) d[mt][nt][e] = 0.f;

    for (int ko = 0; ko < 16; ko++) {
        __syncthreads();
#pragma unroll
        for (int i = 0; i < 8; i++) {
            int f   = tid + i * 256;
            int row = f >> 4;
            int c4  = (f & 15) << 2;
            float4 v = *(const float4*)&X[(size_t)(r0 + row) * Dd + ko * 64 + c4];
            float xs[4] = {v.x, v.y, v.z, v.w};
            __nv_bfloat16 h[4], l[4];
#pragma unroll
            for (int e = 0; e < 4; e++) {
                h[e] = __float2bfloat16(xs[e]);
                l[e] = __float2bfloat16(xs[e] - __bfloat162float(h[e]));
            }
            uint32_t off = swz_rb(row, c4 * 2);
            asm volatile("st.shared.b64 [%0], %1;" :: "r"(sAh + off), "l"(*(u64*)h) : "memory");
            asm volatile("st.shared.b64 [%0], %1;" :: "r"(sAl + off), "l"(*(u64*)l) : "memory");
        }
#pragma unroll
        for (int i = 0; i < 12; i++) {
            int f   = tid + i * 256;
            int row = f >> 4;
            int c4  = (f & 15) << 2;
            u64 hv = *(const u64*)&g_wh[(size_t)row * Dd + ko * 64 + c4];
            u64 lv = *(const u64*)&g_wl[(size_t)row * Dd + ko * 64 + c4];
            uint32_t off = swz_rb(row, c4 * 2);
            asm volatile("st.shared.b64 [%0], %1;" :: "r"(sBh + off), "l"(hv) : "memory");
            asm volatile("st.shared.b64 [%0], %1;" :: "r"(sBl + off), "l"(lv) : "memory");
        }
        __syncthreads();

#pragma unroll
        for (int s = 0; s < 4; s++) {
            const int j = s * 2 + ahalf;
            uint32_t ah[4][4], al[4][4];
#pragma unroll
            for (int mt = 0; mt < 4; mt++) {
                uint32_t off = swz_rj(m0 + mt * 16 + arow, j);
                ldmx4(ah[mt], sAh + off);
                ldmx4(al[mt], sAl + off);
            }
            uint32_t bh[6][2], bl[6][2];
#pragma unroll
            for (int p = 0; p < 3; p++) {
                uint32_t off = swz_rj(n0 + p * 16 + arow, j);
                uint32_t t[4];
                ldmx4(t, sBh + off);
                bh[2*p][0] = t[0]; bh[2*p][1] = t[2];
                bh[2*p+1][0] = t[1]; bh[2*p+1][1] = t[3];
                ldmx4(t, sBl + off);
                bl[2*p][0] = t[0]; bl[2*p][1] = t[2];
                bl[2*p+1][0] = t[1]; bl[2*p+1][1] = t[3];
            }
#pragma unroll
            for (int mt = 0; mt < 4; mt++)
#pragma unroll
                for (int nt = 0; nt < 6; nt++) {
                    mma16816(d[mt][nt], ah[mt], bh[nt][0], bh[nt][1]);
                    mma16816(d[mt][nt], ah[mt], bl[nt][0], bl[nt][1]);
                    mma16816(d[mt][nt], al[mt], bh[nt][0], bh[nt][1]);
                }
        }
    }

#pragma unroll
    for (int mt = 0; mt < 4; mt++) {
        const int rb0 = r0 + m0 + mt * 16 + (lane >> 2);
#pragma unroll
        for (int nt = 0; nt < 6; nt++) {
            const int cb = n0 + nt * 8;
            const int lc = (cb & 63) + ((lane & 3) << 1);
#pragma unroll
            for (int half = 0; half < 2; half++) {
                const size_t row = (size_t)(rb0 + half * 8);
                float v0 = d[mt][nt][2*half], v1 = d[mt][nt][2*half + 1];
                if (cb < 64) {
                    v0 *= QSCALE; v1 *= QSCALE;
                    uint32_t h = bfpack(v0, v1);
                    uint32_t l = bfpack(v0 - __bfloat162float(((__nv_bfloat162*)&h)->x),
                                        v1 - __bfloat162float(((__nv_bfloat162*)&h)->y));
                    *(uint32_t*)&g_qh[row * Hh + lc] = h;
                    *(uint32_t*)&g_ql[row * Hh + lc] = l;
                } else if (cb < 128) {
                    uint32_t h = bfpack(v0, v1);
                    uint32_t l = bfpack(v0 - __bfloat162float(((__nv_bfloat162*)&h)->x),
                                        v1 - __bfloat162float(((__nv_bfloat162*)&h)->y));
                    *(uint32_t*)&g_kh[row * Hh + lc] = h;
                    *(uint32_t*)&g_kl[row * Hh + lc] = l;
                } else {
                    *(float2*)&g_v[row * Hh + lc] = make_float2(v0, v1);
                }
            }
        }
    }
}

// ---------------------------------------------------------------------------
__global__ __launch_bounds__(256) void conv_vt_kernel()
{
    __shared__ float ts[64][65];
    const int s0  = blockIdx.x * 64;
    const int b   = blockIdx.z;
    const int tid = threadIdx.x;
#pragma unroll
    for (int i = 0; i < 16; i++) {
        int f = tid + i * 256;
        int r = f >> 6, d = f & 63;
        ts[r][d] = g_v[(size_t)(b * Ls + s0 + r) * Hh + d];
    }
    __syncthreads();
#pragma unroll
    for (int i = 0; i < 16; i++) {
        int f = tid + i * 256;
        int d = f >> 6, r = f & 63;
        float v = ts[r][d];
        __nv_bfloat16 h = __float2bfloat16(v);
        size_t o = (size_t)(b * Hh + d) * Ls + s0 + r;
        g_vh[o] = h;
        g_vl[o] = __float2bfloat16(v - __bfloat162float(h));
    }
}

// ---------------------------------------------------------------------------
// HMMA flash attention: qtile 128 (8 warps x 16 rows), chunk 512, batch.
// cp.async double-buffered K/V staging; log2-domain softmax; per-warp causal
// tile skip (warps below a key tile skip its MMAs entirely).
// ---------------------------------------------------------------------------
__global__ __launch_bounds__(256, 2) void attnB_kernel()
{
    extern __shared__ __align__(1024) char sm[];
    const uint32_t s0b = smem_u32(sm);

    const int qtile = blockIdx.x;
    const int c     = blockIdx.y;
    const int b     = blockIdx.z;
    const int q0    = qtile << 7;              // 128-query tiles
    const int cbase = c << 9;                  // 512-key chunks
    if (cbase > q0) return;

    const int tid   = threadIdx.x;
    const int wid   = tid >> 5;
    const int lane  = tid & 31;
    const int m0    = wid << 4;                // warp rows q0+m0 .. q0+m0+15
    const int arow  = lane & 15;
    const int ahalf = lane >> 4;
    const int g     = lane >> 2;
    const int tig   = lane & 3;
    const int qrmin = q0 + m0;
    const int qrmax = qrmin + 15;

    // ---- stage Q tile (128 rows, hi at s0b, lo at s0b+16K), extract frags ----
#pragma unroll
    for (int i = 0; i < 8; i++) {
        int f   = tid + i * 256;               // 0..2047 u64s (128 rows x 16)
        int row = f >> 4;
        int c4  = (f & 15) << 2;
        u64 hv = *(const u64*)&g_qh[(size_t)(b * Ls + q0 + row) * Hh + c4];
        u64 lv = *(const u64*)&g_ql[(size_t)(b * Ls + q0 + row) * Hh + c4];
        uint32_t off = swz_rb(row, c4 * 2);
        asm volatile("st.shared.b64 [%0], %1;" :: "r"(s0b + off), "l"(hv) : "memory");
        asm volatile("st.shared.b64 [%0], %1;" :: "r"(s0b + 16384 + off), "l"(lv) : "memory");
    }
    __syncthreads();
    uint32_t qh[4][4], ql[4][4];
#pragma unroll
    for (int s = 0; s < 4; s++) {
        int j = 2 * s + ahalf;
        ldmx4(qh[s], s0b + swz_rj(m0 + arow, j));
        ldmx4(ql[s], s0b + 16384 + swz_rj(m0 + arow, j));
    }
    __syncthreads();

    float O[8][4];
#pragma unroll
    for (int nt = 0; nt < 8; nt++)
#pragma unroll
        for (int e = 0; e < 4; e++) O[nt][e] = 0.f;
    float mr0 = -1e30f, mr1 = -1e30f, l0 = 0.f, l1 = 0.f;

    const int cdiag  = q0 >> 9;
    const int ntiles = (c < cdiag) ? 8 : (((q0 + 127 - cbase) >> 6) + 1);

    auto stage = [&](int buf, int kstart) {
        const uint32_t base = s0b + buf * 32768;
#pragma unroll
        for (int i = 0; i < 2; i++) {
            int f   = tid + i * 256;           // 0..511
            int row = f >> 3;
            int j   = f & 7;
            uint32_t off = (uint32_t)(row * 128 + ((j ^ (row & 7)) << 4));
            CPA16(base + off,         (const char*)&g_kh[(size_t)(b * Ls + kstart + row) * Hh + j * 8]);
            CPA16(base + 8192 + off,  (const char*)&g_kl[(size_t)(b * Ls + kstart + row) * Hh + j * 8]);
            CPA16(base + 16384 + off, (const char*)&g_vh[(size_t)(b * Hh + row) * Ls + kstart + j * 8]);
            CPA16(base + 24576 + off, (const char*)&g_vl[(size_t)(b * Hh + row) * Ls + kstart + j * 8]);
        }
    };

    stage(0, cbase);
    CPA_COMMIT();

    int buf = 0;
    for (int kt = 0; kt < ntiles; kt++) {
        const int kstart = cbase + (kt << 6);
        if (kt + 1 < ntiles) { stage(buf ^ 1, kstart + 64); CPA_COMMIT(); CPA_WAIT(1); }
        else                 { CPA_WAIT(0); }
        __syncthreads();

        if (kstart <= qrmax) {                 // warp has >=1 unmasked key in tile
            const uint32_t sKh = s0b + buf * 32768;
            const uint32_t sKl = sKh + 8192;
            const uint32_t sVh = sKh + 16384;
            const uint32_t sVl = sKh + 24576;

            // ---- S = Q' K^T ----
            float S[8][4];
#pragma unroll
            for (int nt = 0; nt < 8; nt++)
#pragma unroll
                for (int e = 0; e < 4; e++) S[nt][e] = 0.f;
#pragma unroll
            for (int s = 0; s < 4; s++) {
                int j = 2 * s + ahalf;
#pragma unroll
                for (int p = 0; p < 4; p++) {
                    uint32_t th[4], tl[4];
                    ldmx4(th, sKh + swz_rj(p * 16 + arow, j));
                    ldmx4(tl, sKl + swz_rj(p * 16 + arow, j));
                    mma16816(S[2*p],   qh[s], th[0], th[2]);
                    mma16816(S[2*p],   qh[s], tl[0], tl[2]);
                    mma16816(S[2*p],   ql[s], th[0], th[2]);
                    mma16816(S[2*p+1], qh[s], th[1], th[3]);
                    mma16816(S[2*p+1], qh[s], tl[1], tl[3]);
                    mma16816(S[2*p+1], ql[s], th[1], th[3]);
                }
            }
            // ---- causal mask when tile straddles this warp's rows ----
            if (kstart + 63 > qrmin) {
                const int qr0 = qrmin + g - kstart;   // query rel to tile keys
                const int qr1 = qr0 + 8;
#pragma unroll
                for (int nt = 0; nt < 8; nt++) {
                    const int kc = nt * 8 + tig * 2;
                    if (kc     > qr0) S[nt][0] = -INFINITY;
                    if (kc + 1 > qr0) S[nt][1] = -INFINITY;
                    if (kc     > qr1) S[nt][2] = -INFINITY;
                    if (kc + 1 > qr1) S[nt][3] = -INFINITY;
                }
            }
            // ---- online softmax (log2 domain) ----
            float rm0 = -INFINITY, rm1 = -INFINITY;
#pragma unroll
            for (int nt = 0; nt < 8; nt++) {
                rm0 = fmaxf(rm0, fmaxf(S[nt][0], S[nt][1]));
                rm1 = fmaxf(rm1, fmaxf(S[nt][2], S[nt][3]));
            }
            rm0 = fmaxf(rm0, __shfl_xor_sync(0xffffffffu, rm0, 1));
            rm0 = fmaxf(rm0, __shfl_xor_sync(0xffffffffu, rm0, 2));
            rm1 = fmaxf(rm1, __shfl_xor_sync(0xffffffffu, rm1, 1));
            rm1 = fmaxf(rm1, __shfl_xor_sync(0xffffffffu, rm1, 2));
            const float mn0 = fmaxf(mr0, rm0);
            const float mn1 = fmaxf(mr1, rm1);
            const float sc0 = ex2(mr0 - mn0);
            const float sc1 = ex2(mr1 - mn1);
            mr0 = mn0; mr1 = mn1;
            l0 *= sc0; l1 *= sc1;
#pragma unroll
            for (int nt = 0; nt < 8; nt++) {
                O[nt][0] *= sc0; O[nt][1] *= sc0;
                O[nt][2] *= sc1; O[nt][3] *= sc1;
            }
#pragma unroll
            for (int nt = 0; nt < 8; nt++) {
                float p0 = ex2(S[nt][0] - mr0);
                float p1 = ex2(S[nt][1] - mr0);
                float p2 = ex2(S[nt][2] - mr1);
                float p3 = ex2(S[nt][3] - mr1);
                l0 += p0 + p1; l1 += p2 + p3;
                S[nt][0] = p0; S[nt][1] = p1; S[nt][2] = p2; S[nt][3] = p3;
            }
            // ---- O += P V ----
#pragma unroll
            for (int t = 0; t < 4; t++) {
                uint32_t ph[4], pl[4];
                {
                    uint32_t h;
                    h = bfpack(S[2*t][0], S[2*t][1]);  ph[0] = h;
                    pl[0] = bfpack(S[2*t][0] - __bfloat162float(((__nv_bfloat162*)&h)->x),
                                   S[2*t][1] - __bfloat162float(((__nv_bfloat162*)&h)->y));
                    h = bfpack(S[2*t][2], S[2*t][3]);  ph[1] = h;
                    pl[1] = bfpack(S[2*t][2] - __bfloat162float(((__nv_bfloat162*)&h)->x),
                                   S[2*t][3] - __bfloat162float(((__nv_bfloat162*)&h)->y));
                    h = bfpack(S[2*t+1][0], S[2*t+1][1]); ph[2] = h;
                    pl[2] = bfpack(S[2*t+1][0] - __bfloat162float(((__nv_bfloat162*)&h)->x),
                                   S[2*t+1][1] - __bfloat162float(((__nv_bfloat162*)&h)->y));
                    h = bfpack(S[2*t+1][2], S[2*t+1][3]); ph[3] = h;
                    pl[3] = bfpack(S[2*t+1][2] - __bfloat162float(((__nv_bfloat162*)&h)->x),
                                   S[2*t+1][3] - __bfloat162float(((__nv_bfloat162*)&h)->y));
                }
                int j = 2 * t + ahalf;
#pragma unroll
                for (int p = 0; p < 4; p++) {
                    uint32_t th[4], tl[4];
                    ldmx4(th, sVh + swz_rj(p * 16 + arow, j));
                    ldmx4(tl, sVl + swz_rj(p * 16 + arow, j));
                    mma16816(O[2*p],   ph, th[0], th[2]);
                    mma16816(O[2*p],   ph, tl[0], tl[2]);
                    mma16816(O[2*p],   pl, th[0], th[2]);
                    mma16816(O[2*p+1], ph, th[1], th[3]);
                    mma16816(O[2*p+1], ph, tl[1], tl[3]);
                    mma16816(O[2*p+1], pl, th[1], th[3]);
                }
            }
        }
        __syncthreads();
        buf ^= 1;
    }

    // ---- finalize + write partials ----
    l0 += __shfl_xor_sync(0xffffffffu, l0, 1);
    l0 += __shfl_xor_sync(0xffffffffu, l0, 2);
    l1 += __shfl_xor_sync(0xffffffffu, l1, 1);
    l1 += __shfl_xor_sync(0xffffffffu, l1, 2);

    const int grow0 = b * Ls + q0 + m0 + g;
    const int grow1 = grow0 + 8;
    const int pidx0 = c * ROWS + grow0;
    const int pidx1 = c * ROWS + grow1;
    if (tig == 0) {
        g_m[pidx0] = mr0; g_l[pidx0] = l0;
        g_m[pidx1] = mr1; g_l[pidx1] = l1;
    }
#pragma unroll
    for (int nt = 0; nt < 8; nt++) {
        const int col = nt * 8 + tig * 2;
        *(float2*)&g_acc[(size_t)pidx0 * Hh + col] = make_float2(O[nt][0], O[nt][1]);
        *(float2*)&g_acc[(size_t)pidx1 * Hh + col] = make_float2(O[nt][2], O[nt][3]);
    }
}

// ---------------------------------------------------------------------------
// Combine: merge <=8 chunk partials per row (log2-domain weights).
// ---------------------------------------------------------------------------
__global__ __launch_bounds__(256) void combine_kernel(float* __restrict__ out)
{
    const int t   = blockIdx.x * blockDim.x + threadIdx.x;
    const int row = t >> 4;
    const int d4  = t & 15;
    const int ll  = row & (Ls - 1);
    const int nch = (ll >> 9) + 1;

    float M = -INFINITY;
#pragma unroll 4
    for (int cc = 0; cc < nch; cc++)
        M = fmaxf(M, g_m[cc * ROWS + row]);

    float  Lt = 0.f;
    float4 o  = make_float4(0.f, 0.f, 0.f, 0.f);
#pragma unroll 4
    for (int cc = 0; cc < nch; cc++) {
        const float w = ex2(g_m[cc * ROWS + row] - M);
        Lt += w * g_l[cc * ROWS + row];
        float4 a = *(const float4*)&g_acc[((size_t)cc * ROWS + row) * Hh + (d4 << 2)];
        o.x = fmaf(w, a.x, o.x); o.y = fmaf(w, a.y, o.y);
        o.z = fmaf(w, a.z, o.z); o.w = fmaf(w, a.w, o.w);
    }
    const float inv = 1.f / Lt;
    o.x *= inv; o.y *= inv; o.z *= inv; o.w *= inv;
    *(float4*)&out[(size_t)row * Hh + (d4 << 2)] = o;
}

// ---------------------------------------------------------------------------
extern "C" void kernel_launch(void* const* d_in, const int* in_sizes, int n_in,
                              void* d_out, int out_size)
{
    const float* x  = (const float*)d_in[0];
    const float* Wq = (const float*)d_in[1];
    const float* Wk = (const float*)d_in[2];
    const float* Wv = (const float*)d_in[3];
    float* out = (float*)d_out;

    cudaFuncSetAttribute(proj_mma_kernel,
                         cudaFuncAttributeMaxDynamicSharedMemorySize, SM_TOTAL);
    cudaFuncSetAttribute(attnB_kernel,
                         cudaFuncAttributeMaxDynamicSharedMemorySize, ATT_SMEM);

    prep_w_kernel<<<(192 * Dd) / 256, 256>>>(Wq, Wk, Wv);
    proj_mma_kernel<<<ROWS / 128, 256, SM_TOTAL>>>(x);
    {
        dim3 vg(Ls / 64, 1, Bb);
        conv_vt_kernel<<<vg, 256>>>();
    }
    dim3 ag(Ls / 128, NCH, Bb);
    attnB_kernel<<<ag, 256, ATT_SMEM>>>();

    combine_kernel<<<(ROWS * 16) / 256, 256>>>(out);
}